// round 1
// baseline (speedup 1.0000x reference)
#include <cuda_runtime.h>
#include <cstdint>

#define BB   8
#define NPTS 2048
#define KNN  10
#define MAXF 1024
#define SLOPE 0.2f

// ---------------- static scratch (no allocations allowed) ----------------
__device__ float g_feat_a[BB * NPTS * MAXF];                 // 64 MB
__device__ float g_feat_b[BB * NPTS * MAXF];                 // 64 MB
__device__ float g_center[BB * NPTS * MAXF];                 // 64 MB
__device__ float g_dot[(size_t)BB * NPTS * NPTS];            // 128 MB
__device__ float g_sq[BB * NPTS];
__device__ int   g_idx[BB * NPTS * KNN];
__device__ float g_pool[BB * MAXF];
__device__ float g_m1[BB * 128];
__device__ float g_m2[BB * 64];

// ---------------- dot = X @ X^T per batch (tiled 64x64, fp32) ----------------
__global__ __launch_bounds__(256) void gemm_nt_kernel(const float* __restrict__ Xall,
                                                      float* __restrict__ Call, int Kd) {
    int b = blockIdx.z;
    const float* X = Xall + (size_t)b * NPTS * Kd;
    float* C = Call + (size_t)b * NPTS * NPTS;
    int m0 = blockIdx.y * 64, n0 = blockIdx.x * 64;
    __shared__ float As[16][65];
    __shared__ float Bs[16][65];
    int tid = threadIdx.x;
    int tx = tid & 15, ty = tid >> 4;
    float acc[4][4];
#pragma unroll
    for (int i = 0; i < 4; i++)
#pragma unroll
        for (int j = 0; j < 4; j++) acc[i][j] = 0.f;

    for (int f0 = 0; f0 < Kd; f0 += 16) {
        for (int e = tid; e < 1024; e += 256) {
            int r = e >> 4, f = e & 15;
            bool ok = (f0 + f) < Kd;
            As[f][r] = ok ? X[(size_t)(m0 + r) * Kd + f0 + f] : 0.f;
            Bs[f][r] = ok ? X[(size_t)(n0 + r) * Kd + f0 + f] : 0.f;
        }
        __syncthreads();
#pragma unroll
        for (int f = 0; f < 16; f++) {
            float a[4], bv[4];
#pragma unroll
            for (int u = 0; u < 4; u++) a[u] = As[f][ty + 16 * u];
#pragma unroll
            for (int u = 0; u < 4; u++) bv[u] = Bs[f][tx + 16 * u];
#pragma unroll
            for (int um = 0; um < 4; um++)
#pragma unroll
                for (int un = 0; un < 4; un++) acc[um][un] += a[um] * bv[un];
        }
        __syncthreads();
    }
#pragma unroll
    for (int um = 0; um < 4; um++)
#pragma unroll
        for (int un = 0; un < 4; un++)
            C[(size_t)(m0 + ty + 16 * um) * NPTS + (n0 + tx + 16 * un)] = acc[um][un];
}

// ---------------- squared norms ----------------
__global__ void sq_kernel(const float* __restrict__ X, int Kd) {
    int i = blockIdx.x * blockDim.x + threadIdx.x;
    if (i < BB * NPTS) {
        const float* p = X + (size_t)i * Kd;
        float s = 0.f;
        for (int f = 0; f < Kd; f++) s += p[f] * p[f];
        g_sq[i] = s;
    }
}

// ---------------- top-K smallest d2 per row, warp per row ----------------
__device__ __forceinline__ bool dless(float a, int ia, float bv, int ib) {
    return (a < bv) || (a == bv && ia < ib);
}

__global__ void topk_kernel(const float* __restrict__ dotm) {
    int gwarp = (blockIdx.x * blockDim.x + threadIdx.x) >> 5;
    int lane = threadIdx.x & 31;
    if (gwarp >= BB * NPTS) return;
    int b = gwarp / NPTS, i = gwarp % NPTS;
    const float* drow = dotm + ((size_t)b * NPTS + i) * NPTS;
    float sqi = g_sq[b * NPTS + i];

    float best[KNN];
    int bidx[KNN];
#pragma unroll
    for (int m = 0; m < KNN; m++) { best[m] = 3.0e38f; bidx[m] = 0x7fffffff; }

    for (int j = lane; j < NPTS; j += 32) {
        float d2 = sqi + g_sq[b * NPTS + j] - 2.0f * drow[j];
        if (dless(d2, j, best[KNN - 1], bidx[KNN - 1])) {
            int m = KNN - 1;
#pragma unroll
            for (int t = KNN - 1; t > 0; t--) {
                if (m == t && dless(d2, j, best[t - 1], bidx[t - 1])) {
                    best[t] = best[t - 1]; bidx[t] = bidx[t - 1]; m = t - 1;
                }
            }
            best[m] = d2; bidx[m] = j;
        }
    }

    int ptr = 0;
    for (int r = 0; r < KNN; r++) {
        float v = (ptr < KNN) ? best[ptr] : 3.0e38f;
        int jj = (ptr < KNN) ? bidx[ptr] : 0x7fffffff;
        float mv = v; int mj = jj;
#pragma unroll
        for (int off = 16; off > 0; off >>= 1) {
            float ov = __shfl_down_sync(0xffffffffu, mv, off);
            int oj = __shfl_down_sync(0xffffffffu, mj, off);
            if (dless(ov, oj, mv, mj)) { mv = ov; mj = oj; }
        }
        mv = __shfl_sync(0xffffffffu, mv, 0);
        mj = __shfl_sync(0xffffffffu, mj, 0);
        if (jj == mj && v == mv) ptr++;
        if (lane == 0) g_idx[((size_t)b * NPTS + i) * KNN + r] = mj;
    }
}

// ---------------- center GEMM: C = A @ W1 + bias (tiled 64x64) ----------------
__global__ __launch_bounds__(256) void gemm_nn_kernel(const float* __restrict__ A,
                                                      const float* __restrict__ W,
                                                      const float* __restrict__ bias,
                                                      float* __restrict__ C,
                                                      int Kd, int Nn) {
    int m0 = blockIdx.y * 64, o0 = blockIdx.x * 64;
    __shared__ float As[16][65];
    __shared__ float Ws[16][64];
    int tid = threadIdx.x;
    int tx = tid & 15, ty = tid >> 4;
    float acc[4][4];
#pragma unroll
    for (int i = 0; i < 4; i++)
#pragma unroll
        for (int j = 0; j < 4; j++) acc[i][j] = 0.f;

    for (int f0 = 0; f0 < Kd; f0 += 16) {
        for (int e = tid; e < 1024; e += 256) {
            int r = e >> 4, f = e & 15;
            As[f][r] = ((f0 + f) < Kd) ? A[(size_t)(m0 + r) * Kd + f0 + f] : 0.f;
        }
        for (int e = tid; e < 1024; e += 256) {
            int f = e >> 6, o = e & 63;
            Ws[f][o] = ((f0 + f) < Kd) ? W[(size_t)(f0 + f) * Nn + o0 + o] : 0.f;
        }
        __syncthreads();
#pragma unroll
        for (int f = 0; f < 16; f++) {
            float a[4], bv[4];
#pragma unroll
            for (int u = 0; u < 4; u++) a[u] = As[f][ty + 16 * u];
#pragma unroll
            for (int u = 0; u < 4; u++) bv[u] = Ws[f][tx + 16 * u];
#pragma unroll
            for (int um = 0; um < 4; um++)
#pragma unroll
                for (int un = 0; un < 4; un++) acc[um][un] += a[um] * bv[un];
        }
        __syncthreads();
    }
#pragma unroll
    for (int um = 0; um < 4; um++)
#pragma unroll
        for (int un = 0; un < 4; un++) {
            int o = o0 + tx + 16 * un;
            C[(size_t)(m0 + ty + 16 * um) * Nn + o] = acc[um][un] + bias[o];
        }
}

// ---------------- fused edge conv: gather diff, GEMM vs W2, +center, leaky, max over K ----
// block: 16 points x 64 outputs, 256 threads (ty=point, tx=output lane, 4 outputs/thread)
#define EP 16
#define EO 64
#define ETK 16
__global__ __launch_bounds__(256) void edge_kernel(const float* __restrict__ X,
                                                   const int* __restrict__ idx,
                                                   const float* __restrict__ W2,
                                                   const float* __restrict__ Cc,
                                                   float* __restrict__ Out,
                                                   int fin, int fout) {
    int b = blockIdx.z;
    int n0 = blockIdx.y * EP;
    int o0 = blockIdx.x * EO;
    int tid = threadIdx.x;
    int tx = tid & 15, ty = tid >> 4;

    __shared__ float sd[EP * KNN][ETK + 1];
    __shared__ float sw[ETK][EO];
    __shared__ int sidx[EP * KNN];

    for (int e = tid; e < EP * KNN; e += 256) {
        int p = e / KNN, k = e % KNN;
        sidx[e] = idx[((size_t)b * NPTS + n0 + p) * KNN + k];
    }
    __syncthreads();

    float acc[KNN][4];
#pragma unroll
    for (int k = 0; k < KNN; k++)
#pragma unroll
        for (int u = 0; u < 4; u++) acc[k][u] = 0.f;

    for (int f0 = 0; f0 < fin; f0 += ETK) {
        // diff tile: 160 rows x 16 f
        for (int e = tid; e < EP * KNN * ETK; e += 256) {
            int r = e >> 4, f = e & 15;
            float v = 0.f;
            if (f0 + f < fin) {
                int p = r / KNN;
                int j = sidx[r];
                float xj = X[((size_t)b * NPTS + j) * fin + f0 + f];
                float xc = X[((size_t)b * NPTS + n0 + p) * fin + f0 + f];
                v = xj - xc;
            }
            sd[r][f] = v;
        }
        // W2 tile: 16 f x 64 o
        for (int e = tid; e < ETK * EO; e += 256) {
            int f = e >> 6, o = e & 63;
            sw[f][o] = ((f0 + f) < fin) ? W2[(size_t)(f0 + f) * fout + o0 + o] : 0.f;
        }
        __syncthreads();
#pragma unroll
        for (int f = 0; f < ETK; f++) {
            float w[4];
#pragma unroll
            for (int u = 0; u < 4; u++) w[u] = sw[f][tx + 16 * u];
#pragma unroll
            for (int k = 0; k < KNN; k++) {
                float d = sd[ty * KNN + k][f];
#pragma unroll
                for (int u = 0; u < 4; u++) acc[k][u] += d * w[u];
            }
        }
        __syncthreads();
    }

    int n = n0 + ty;
#pragma unroll
    for (int u = 0; u < 4; u++) {
        int o = o0 + tx + 16 * u;
        float cv = Cc[((size_t)b * NPTS + n) * fout + o];
        float m = -3.0e38f;
#pragma unroll
        for (int k = 0; k < KNN; k++) {
            float h = cv + acc[k][u];
            h = (h > 0.f) ? h : SLOPE * h;
            m = fmaxf(m, h);
        }
        Out[((size_t)b * NPTS + n) * fout + o] = m;
    }
}

// ---------------- global max pool over N ----------------
__global__ void pool_kernel(const float* __restrict__ H, int Fo) {
    int b = blockIdx.y;
    int o = blockIdx.x * blockDim.x + threadIdx.x;
    if (o < Fo) {
        float m = -3.0e38f;
        for (int n = 0; n < NPTS; n++)
            m = fmaxf(m, H[((size_t)b * NPTS + n) * Fo + o]);
        g_pool[b * Fo + o] = m;
    }
}

// ---------------- small MLP layer (no activation per reference) ----------------
__global__ void mlp_kernel(const float* __restrict__ A, const float* __restrict__ W,
                           const float* __restrict__ bias, float* __restrict__ C,
                           int M, int Kd, int Nn) {
    for (int i = threadIdx.x; i < M * Nn; i += blockDim.x) {
        int m = i / Nn, o = i % Nn;
        float s = bias[o];
        for (int f = 0; f < Kd; f++) s += A[(size_t)m * Kd + f] * W[(size_t)f * Nn + o];
        C[i] = s;
    }
}

// ---------------- launcher ----------------
extern "C" void kernel_launch(void* const* d_in, const int* in_sizes, int n_in,
                              void* d_out, int out_size) {
    const float* x = (const float*)d_in[0];
    const float* w[5];
    const float* bs[5];
    for (int l = 0; l < 5; l++) {
        w[l] = (const float*)d_in[1 + 2 * l];
        bs[l] = (const float*)d_in[2 + 2 * l];
    }
    const float* m0w = (const float*)d_in[11];
    const float* m0b = (const float*)d_in[12];
    const float* m1w = (const float*)d_in[13];
    const float* m1b = (const float*)d_in[14];
    const float* m2w = (const float*)d_in[15];
    const float* m2b = (const float*)d_in[16];
    float* out = (float*)d_out;

    float *feat_a, *feat_b, *centerp, *dotp, *poolp, *m1p, *m2p;
    cudaGetSymbolAddress((void**)&feat_a, g_feat_a);
    cudaGetSymbolAddress((void**)&feat_b, g_feat_b);
    cudaGetSymbolAddress((void**)&centerp, g_center);
    cudaGetSymbolAddress((void**)&dotp, g_dot);
    cudaGetSymbolAddress((void**)&poolp, g_pool);
    cudaGetSymbolAddress((void**)&m1p, g_m1);
    cudaGetSymbolAddress((void**)&m2p, g_m2);
    int* idxp;
    cudaGetSymbolAddress((void**)&idxp, g_idx);

    const int fins[5] = {3, 64, 128, 256, 512};
    const int fouts[5] = {64, 128, 256, 512, 1024};
    float* bufs[2] = {feat_a, feat_b};

    const float* cur = x;
    for (int l = 0; l < 5; l++) {
        int fin = fins[l], fout = fouts[l];

        gemm_nt_kernel<<<dim3(NPTS / 64, NPTS / 64, BB), 256>>>(cur, dotp, fin);
        sq_kernel<<<(BB * NPTS + 255) / 256, 256>>>(cur, fin);
        topk_kernel<<<(BB * NPTS) / 8, 256>>>(dotp);
        gemm_nn_kernel<<<dim3(fout / 64, (BB * NPTS) / 64), 256>>>(cur, w[l], bs[l], centerp, fin, fout);
        edge_kernel<<<dim3(fout / 64, NPTS / EP, BB), 256>>>(cur, idxp, w[l] + (size_t)fin * fout,
                                                             centerp, bufs[l & 1], fin, fout);
        cur = bufs[l & 1];
    }

    pool_kernel<<<dim3(MAXF / 256, BB), 256>>>(cur, MAXF);
    mlp_kernel<<<1, 1024>>>(poolp, m0w, m0b, m1p, BB, 1024, 128);
    mlp_kernel<<<1, 512>>>(m1p, m1w, m1b, m2p, BB, 128, 64);
    mlp_kernel<<<1, 256>>>(m2p, m2w, m2b, out, BB, 64, 1);
}

// round 2
// speedup vs baseline: 1.9826x; 1.9826x over previous
#include <cuda_runtime.h>
#include <cstdint>

#define BB   8
#define NPTS 2048
#define KNN  10
#define MAXF 1024
#define SLOPE 0.2f

// ---------------- static scratch (no allocations allowed) ----------------
__device__ float g_feat_a[BB * NPTS * MAXF];                 // 64 MB
__device__ float g_feat_b[BB * NPTS * MAXF];                 // 64 MB
__device__ float g_center[BB * NPTS * MAXF];                 // 64 MB
__device__ float g_dot[(size_t)BB * NPTS * NPTS];            // 128 MB (reused as Y after topk)
__device__ float g_sq[BB * NPTS];
__device__ int   g_idx[BB * NPTS * KNN];
__device__ float g_pool[BB * MAXF];
__device__ float g_m1[BB * 128];
__device__ float g_m2[BB * 64];

// ---------------- dot = X @ X^T per batch (tiled 64x64, fp32) ----------------
__global__ __launch_bounds__(256) void gemm_nt_kernel(const float* __restrict__ Xall,
                                                      float* __restrict__ Call, int Kd) {
    int b = blockIdx.z;
    const float* X = Xall + (size_t)b * NPTS * Kd;
    float* C = Call + (size_t)b * NPTS * NPTS;
    int m0 = blockIdx.y * 64, n0 = blockIdx.x * 64;
    __shared__ float As[16][65];
    __shared__ float Bs[16][65];
    int tid = threadIdx.x;
    int tx = tid & 15, ty = tid >> 4;
    float acc[4][4];
#pragma unroll
    for (int i = 0; i < 4; i++)
#pragma unroll
        for (int j = 0; j < 4; j++) acc[i][j] = 0.f;

    for (int f0 = 0; f0 < Kd; f0 += 16) {
        for (int e = tid; e < 1024; e += 256) {
            int r = e >> 4, f = e & 15;
            bool ok = (f0 + f) < Kd;
            As[f][r] = ok ? X[(size_t)(m0 + r) * Kd + f0 + f] : 0.f;
            Bs[f][r] = ok ? X[(size_t)(n0 + r) * Kd + f0 + f] : 0.f;
        }
        __syncthreads();
#pragma unroll
        for (int f = 0; f < 16; f++) {
            float a[4], bv[4];
#pragma unroll
            for (int u = 0; u < 4; u++) a[u] = As[f][ty + 16 * u];
#pragma unroll
            for (int u = 0; u < 4; u++) bv[u] = Bs[f][tx + 16 * u];
#pragma unroll
            for (int um = 0; um < 4; um++)
#pragma unroll
                for (int un = 0; un < 4; un++) acc[um][un] += a[um] * bv[un];
        }
        __syncthreads();
    }
#pragma unroll
    for (int um = 0; um < 4; um++)
#pragma unroll
        for (int un = 0; un < 4; un++)
            C[(size_t)(m0 + ty + 16 * um) * NPTS + (n0 + tx + 16 * un)] = acc[um][un];
}

// ---------------- squared norms ----------------
__global__ void sq_kernel(const float* __restrict__ X, int Kd) {
    int i = blockIdx.x * blockDim.x + threadIdx.x;
    if (i < BB * NPTS) {
        const float* p = X + (size_t)i * Kd;
        float s = 0.f;
        for (int f = 0; f < Kd; f++) s += p[f] * p[f];
        g_sq[i] = s;
    }
}

// ---------------- top-K smallest d2 per row, warp per row ----------------
__device__ __forceinline__ bool dless(float a, int ia, float bv, int ib) {
    return (a < bv) || (a == bv && ia < ib);
}

__global__ void topk_kernel(const float* __restrict__ dotm) {
    int gwarp = (blockIdx.x * blockDim.x + threadIdx.x) >> 5;
    int lane = threadIdx.x & 31;
    if (gwarp >= BB * NPTS) return;
    int b = gwarp / NPTS, i = gwarp % NPTS;
    const float* drow = dotm + ((size_t)b * NPTS + i) * NPTS;
    float sqi = g_sq[b * NPTS + i];

    float best[KNN];
    int bidx[KNN];
#pragma unroll
    for (int m = 0; m < KNN; m++) { best[m] = 3.0e38f; bidx[m] = 0x7fffffff; }

    for (int j = lane; j < NPTS; j += 32) {
        float d2 = sqi + g_sq[b * NPTS + j] - 2.0f * drow[j];
        if (dless(d2, j, best[KNN - 1], bidx[KNN - 1])) {
            int m = KNN - 1;
#pragma unroll
            for (int t = KNN - 1; t > 0; t--) {
                if (m == t && dless(d2, j, best[t - 1], bidx[t - 1])) {
                    best[t] = best[t - 1]; bidx[t] = bidx[t - 1]; m = t - 1;
                }
            }
            best[m] = d2; bidx[m] = j;
        }
    }

    int ptr = 0;
    for (int r = 0; r < KNN; r++) {
        float v = (ptr < KNN) ? best[ptr] : 3.0e38f;
        int jj = (ptr < KNN) ? bidx[ptr] : 0x7fffffff;
        float mv = v; int mj = jj;
#pragma unroll
        for (int off = 16; off > 0; off >>= 1) {
            float ov = __shfl_down_sync(0xffffffffu, mv, off);
            int oj = __shfl_down_sync(0xffffffffu, mj, off);
            if (dless(ov, oj, mv, mj)) { mv = ov; mj = oj; }
        }
        mv = __shfl_sync(0xffffffffu, mv, 0);
        mj = __shfl_sync(0xffffffffu, mj, 0);
        if (jj == mj && v == mv) ptr++;
        if (lane == 0) g_idx[((size_t)b * NPTS + i) * KNN + r] = mj;
    }
}

// ---------------- GEMM: C = A @ W + bias (tiled 64x64); bias may be null ----------------
__global__ __launch_bounds__(256) void gemm_nn_kernel(const float* __restrict__ A,
                                                      const float* __restrict__ W,
                                                      const float* __restrict__ bias,
                                                      float* __restrict__ C,
                                                      int Kd, int Nn) {
    int m0 = blockIdx.y * 64, o0 = blockIdx.x * 64;
    __shared__ float As[16][65];
    __shared__ float Ws[16][64];
    int tid = threadIdx.x;
    int tx = tid & 15, ty = tid >> 4;
    float acc[4][4];
#pragma unroll
    for (int i = 0; i < 4; i++)
#pragma unroll
        for (int j = 0; j < 4; j++) acc[i][j] = 0.f;

    for (int f0 = 0; f0 < Kd; f0 += 16) {
        for (int e = tid; e < 1024; e += 256) {
            int r = e >> 4, f = e & 15;
            As[f][r] = ((f0 + f) < Kd) ? A[(size_t)(m0 + r) * Kd + f0 + f] : 0.f;
        }
        for (int e = tid; e < 1024; e += 256) {
            int f = e >> 6, o = e & 63;
            Ws[f][o] = ((f0 + f) < Kd) ? W[(size_t)(f0 + f) * Nn + o0 + o] : 0.f;
        }
        __syncthreads();
#pragma unroll
        for (int f = 0; f < 16; f++) {
            float a[4], bv[4];
#pragma unroll
            for (int u = 0; u < 4; u++) a[u] = As[f][ty + 16 * u];
#pragma unroll
            for (int u = 0; u < 4; u++) bv[u] = Ws[f][tx + 16 * u];
#pragma unroll
            for (int um = 0; um < 4; um++)
#pragma unroll
                for (int un = 0; un < 4; un++) acc[um][un] += a[um] * bv[un];
        }
        __syncthreads();
    }
#pragma unroll
    for (int um = 0; um < 4; um++)
#pragma unroll
        for (int un = 0; un < 4; un++) {
            int o = o0 + tx + 16 * un;
            float bv = bias ? bias[o] : 0.f;
            C[(size_t)(m0 + ty + 16 * um) * Nn + o] = acc[um][un] + bv;
        }
}

// ---------------- gather-max edge conv epilogue ----------------
// out[n,o] = leaky( Z[n,o] - Y[n,o] + max_{j in knn(n)} Y[j,o] )
__global__ __launch_bounds__(256) void gathermax_kernel(const float* __restrict__ Z,
                                                        const float* __restrict__ Y,
                                                        const int* __restrict__ idx,
                                                        float* __restrict__ Out,
                                                        int fout) {
    int bn = blockIdx.x;             // b*NPTS + n
    int b = bn >> 11;
    const int* ip = idx + (size_t)bn * KNN;
    __shared__ int nb[KNN];
    if (threadIdx.x < KNN) nb[threadIdx.x] = ip[threadIdx.x];
    __syncthreads();

    const float* Yb = Y + (size_t)b * NPTS * fout;
    size_t base = (size_t)bn * fout;

    for (int o = threadIdx.x * 4; o < fout; o += blockDim.x * 4) {
        float4 m = make_float4(-3.0e38f, -3.0e38f, -3.0e38f, -3.0e38f);
#pragma unroll
        for (int k = 0; k < KNN; k++) {
            float4 v = *(const float4*)(Yb + (size_t)nb[k] * fout + o);
            m.x = fmaxf(m.x, v.x);
            m.y = fmaxf(m.y, v.y);
            m.z = fmaxf(m.z, v.z);
            m.w = fmaxf(m.w, v.w);
        }
        float4 z = *(const float4*)(Z + base + o);
        float4 y = *(const float4*)(Y + base + o);
        float4 h;
        h.x = z.x - y.x + m.x;
        h.y = z.y - y.y + m.y;
        h.z = z.z - y.z + m.z;
        h.w = z.w - y.w + m.w;
        h.x = (h.x > 0.f) ? h.x : SLOPE * h.x;
        h.y = (h.y > 0.f) ? h.y : SLOPE * h.y;
        h.z = (h.z > 0.f) ? h.z : SLOPE * h.z;
        h.w = (h.w > 0.f) ? h.w : SLOPE * h.w;
        *(float4*)(Out + base + o) = h;
    }
}

// ---------------- global max pool over N ----------------
__global__ void pool_kernel(const float* __restrict__ H, int Fo) {
    int b = blockIdx.y;
    int o = blockIdx.x * blockDim.x + threadIdx.x;
    if (o < Fo) {
        float m = -3.0e38f;
        for (int n = 0; n < NPTS; n++)
            m = fmaxf(m, H[((size_t)b * NPTS + n) * Fo + o]);
        g_pool[b * Fo + o] = m;
    }
}

// ---------------- small MLP layer (no activation per reference) ----------------
__global__ void mlp_kernel(const float* __restrict__ A, const float* __restrict__ W,
                           const float* __restrict__ bias, float* __restrict__ C,
                           int M, int Kd, int Nn) {
    for (int i = threadIdx.x; i < M * Nn; i += blockDim.x) {
        int m = i / Nn, o = i % Nn;
        float s = bias[o];
        for (int f = 0; f < Kd; f++) s += A[(size_t)m * Kd + f] * W[(size_t)f * Nn + o];
        C[i] = s;
    }
}

// ---------------- launcher ----------------
extern "C" void kernel_launch(void* const* d_in, const int* in_sizes, int n_in,
                              void* d_out, int out_size) {
    const float* x = (const float*)d_in[0];
    const float* w[5];
    const float* bs[5];
    for (int l = 0; l < 5; l++) {
        w[l] = (const float*)d_in[1 + 2 * l];
        bs[l] = (const float*)d_in[2 + 2 * l];
    }
    const float* m0w = (const float*)d_in[11];
    const float* m0b = (const float*)d_in[12];
    const float* m1w = (const float*)d_in[13];
    const float* m1b = (const float*)d_in[14];
    const float* m2w = (const float*)d_in[15];
    const float* m2b = (const float*)d_in[16];
    float* out = (float*)d_out;

    float *feat_a, *feat_b, *centerp, *dotp, *poolp, *m1p, *m2p;
    cudaGetSymbolAddress((void**)&feat_a, g_feat_a);
    cudaGetSymbolAddress((void**)&feat_b, g_feat_b);
    cudaGetSymbolAddress((void**)&centerp, g_center);
    cudaGetSymbolAddress((void**)&dotp, g_dot);
    cudaGetSymbolAddress((void**)&poolp, g_pool);
    cudaGetSymbolAddress((void**)&m1p, g_m1);
    cudaGetSymbolAddress((void**)&m2p, g_m2);
    int* idxp;
    cudaGetSymbolAddress((void**)&idxp, g_idx);

    const int fins[5] = {3, 64, 128, 256, 512};
    const int fouts[5] = {64, 128, 256, 512, 1024};
    float* bufs[2] = {feat_a, feat_b};

    const float* cur = x;
    for (int l = 0; l < 5; l++) {
        int fin = fins[l], fout = fouts[l];
        float* yp = dotp;   // reuse dot scratch for Y after topk consumes it

        gemm_nt_kernel<<<dim3(NPTS / 64, NPTS / 64, BB), 256>>>(cur, dotp, fin);
        sq_kernel<<<(BB * NPTS + 255) / 256, 256>>>(cur, fin);
        topk_kernel<<<(BB * NPTS) / 8, 256>>>(dotp);
        // Z = X*W1 + b
        gemm_nn_kernel<<<dim3(fout / 64, (BB * NPTS) / 64), 256>>>(cur, w[l], bs[l], centerp, fin, fout);
        // Y = X*W2 (overwrites dot scratch; topk already done in stream order)
        gemm_nn_kernel<<<dim3(fout / 64, (BB * NPTS) / 64), 256>>>(cur, w[l] + (size_t)fin * fout,
                                                                   nullptr, yp, fin, fout);
        gathermax_kernel<<<BB * NPTS, 256>>>(centerp, yp, idxp, bufs[l & 1], fout);
        cur = bufs[l & 1];
    }

    pool_kernel<<<dim3(MAXF / 256, BB), 256>>>(cur, MAXF);
    mlp_kernel<<<1, 1024>>>(poolp, m0w, m0b, m1p, BB, 1024, 128);
    mlp_kernel<<<1, 512>>>(m1p, m1w, m1b, m2p, BB, 128, 64);
    mlp_kernel<<<1, 256>>>(m2p, m2w, m2b, out, BB, 64, 1);
}

// round 3
// speedup vs baseline: 2.6266x; 1.3248x over previous
#include <cuda_runtime.h>
#include <cstdint>

#define BB   8
#define NPTS 2048
#define KNN  10
#define MAXF 1024
#define SLOPE 0.2f
#define KT   16

// ---------------- static scratch (no allocations allowed) ----------------
__device__ float g_feat_a[BB * NPTS * MAXF];                 // 64 MB
__device__ float g_feat_b[BB * NPTS * MAXF];                 // 64 MB
__device__ float g_center[BB * NPTS * MAXF];                 // 64 MB
__device__ float g_dot[(size_t)BB * NPTS * NPTS];            // 128 MB (reused as Y after topk)
__device__ float g_sq[BB * NPTS];
__device__ int   g_idx[BB * NPTS * KNN];
__device__ float g_pool[BB * MAXF];
__device__ float g_m1[BB * 128];
__device__ float g_m2[BB * 64];

// =====================================================================
// 128x128 register-blocked SGEMM, NN: C[M,Nn] = A[M,Kd] @ W[Kd,Nn] (+bias)
// 256 threads, 8x8 acc per thread, KT=16.
// =====================================================================
__global__ __launch_bounds__(256) void sgemm_nn(const float* __restrict__ A,
                                                const float* __restrict__ W,
                                                const float* __restrict__ bias,
                                                float* __restrict__ C,
                                                int Kd, int Nn) {
    __shared__ float As[KT][128];
    __shared__ float Bs[KT][128];
    int tid = threadIdx.x;
    int tx = tid & 15, ty = tid >> 4;
    int m0 = blockIdx.y * 128, o0 = blockIdx.x * 128;
    const bool kfast = (Kd % KT) == 0;

    float acc[8][8];
#pragma unroll
    for (int i = 0; i < 8; i++)
#pragma unroll
        for (int j = 0; j < 8; j++) acc[i][j] = 0.f;

    for (int f0 = 0; f0 < Kd; f0 += KT) {
        // ---- A tile: 128 rows x KT ----
#pragma unroll
        for (int it = 0; it < 2; it++) {
            int e = tid + it * 256;          // 0..511
            int r = e >> 2;
            int kb = (e & 3) * 4;
            if (kfast) {
                float4 v = *(const float4*)(A + (size_t)(m0 + r) * Kd + f0 + kb);
                As[kb + 0][r] = v.x; As[kb + 1][r] = v.y;
                As[kb + 2][r] = v.z; As[kb + 3][r] = v.w;
            } else {
#pragma unroll
                for (int j = 0; j < 4; j++) {
                    int f = f0 + kb + j;
                    As[kb + j][r] = (f < Kd) ? A[(size_t)(m0 + r) * Kd + f] : 0.f;
                }
            }
        }
        // ---- W tile: KT x 128 ----
#pragma unroll
        for (int it = 0; it < 2; it++) {
            int e = tid + it * 256;
            int k = e >> 5;
            int ob = (e & 31) * 4;
            float4 v = make_float4(0.f, 0.f, 0.f, 0.f);
            if ((f0 + k) < Kd && (o0 + ob) < Nn)
                v = *(const float4*)(W + (size_t)(f0 + k) * Nn + o0 + ob);
            *(float4*)&Bs[k][ob] = v;
        }
        __syncthreads();
#pragma unroll
        for (int k = 0; k < KT; k++) {
            float a[8], b[8];
            *(float4*)&a[0] = *(const float4*)&As[k][ty * 8];
            *(float4*)&a[4] = *(const float4*)&As[k][ty * 8 + 4];
            *(float4*)&b[0] = *(const float4*)&Bs[k][tx * 8];
            *(float4*)&b[4] = *(const float4*)&Bs[k][tx * 8 + 4];
#pragma unroll
            for (int i = 0; i < 8; i++)
#pragma unroll
                for (int j = 0; j < 8; j++) acc[i][j] += a[i] * b[j];
        }
        __syncthreads();
    }

    int oc = o0 + tx * 8;
    if (oc < Nn) {
#pragma unroll
        for (int i = 0; i < 8; i++) {
            size_t row = (size_t)(m0 + ty * 8 + i) * Nn;
            float4 v0, v1;
            float b0 = bias ? bias[oc + 0] : 0.f, b1 = bias ? bias[oc + 1] : 0.f;
            float b2 = bias ? bias[oc + 2] : 0.f, b3 = bias ? bias[oc + 3] : 0.f;
            float b4 = bias ? bias[oc + 4] : 0.f, b5 = bias ? bias[oc + 5] : 0.f;
            float b6 = bias ? bias[oc + 6] : 0.f, b7 = bias ? bias[oc + 7] : 0.f;
            v0 = make_float4(acc[i][0] + b0, acc[i][1] + b1, acc[i][2] + b2, acc[i][3] + b3);
            v1 = make_float4(acc[i][4] + b4, acc[i][5] + b5, acc[i][6] + b6, acc[i][7] + b7);
            *(float4*)(C + row + oc) = v0;
            *(float4*)(C + row + oc + 4) = v1;
        }
    }
}

// =====================================================================
// Symmetric NT SGEMM per batch: C = X @ X^T, only upper tiles computed,
// mirrored into lower half. 128x128 tiles, 8x8 per thread.
// =====================================================================
__global__ __launch_bounds__(256) void sgemm_nt_sym(const float* __restrict__ Xall,
                                                    float* __restrict__ Call, int Kd) {
    int m0 = blockIdx.y * 128, n0 = blockIdx.x * 128;
    if (n0 < m0) return;                      // upper triangle only
    int b = blockIdx.z;
    const float* X = Xall + (size_t)b * NPTS * Kd;
    float* C = Call + (size_t)b * NPTS * NPTS;

    __shared__ float As[KT][128];
    __shared__ float Bs[KT][128];
    int tid = threadIdx.x;
    int tx = tid & 15, ty = tid >> 4;
    const bool kfast = (Kd % KT) == 0;

    float acc[8][8];
#pragma unroll
    for (int i = 0; i < 8; i++)
#pragma unroll
        for (int j = 0; j < 8; j++) acc[i][j] = 0.f;

    for (int f0 = 0; f0 < Kd; f0 += KT) {
#pragma unroll
        for (int it = 0; it < 2; it++) {
            int e = tid + it * 256;
            int r = e >> 2;
            int kb = (e & 3) * 4;
            if (kfast) {
                float4 va = *(const float4*)(X + (size_t)(m0 + r) * Kd + f0 + kb);
                As[kb + 0][r] = va.x; As[kb + 1][r] = va.y;
                As[kb + 2][r] = va.z; As[kb + 3][r] = va.w;
                float4 vb = *(const float4*)(X + (size_t)(n0 + r) * Kd + f0 + kb);
                Bs[kb + 0][r] = vb.x; Bs[kb + 1][r] = vb.y;
                Bs[kb + 2][r] = vb.z; Bs[kb + 3][r] = vb.w;
            } else {
#pragma unroll
                for (int j = 0; j < 4; j++) {
                    int f = f0 + kb + j;
                    As[kb + j][r] = (f < Kd) ? X[(size_t)(m0 + r) * Kd + f] : 0.f;
                    Bs[kb + j][r] = (f < Kd) ? X[(size_t)(n0 + r) * Kd + f] : 0.f;
                }
            }
        }
        __syncthreads();
#pragma unroll
        for (int k = 0; k < KT; k++) {
            float a[8], bv[8];
            *(float4*)&a[0] = *(const float4*)&As[k][ty * 8];
            *(float4*)&a[4] = *(const float4*)&As[k][ty * 8 + 4];
            *(float4*)&bv[0] = *(const float4*)&Bs[k][tx * 8];
            *(float4*)&bv[4] = *(const float4*)&Bs[k][tx * 8 + 4];
#pragma unroll
            for (int i = 0; i < 8; i++)
#pragma unroll
                for (int j = 0; j < 8; j++) acc[i][j] += a[i] * bv[j];
        }
        __syncthreads();
    }

    // normal store (upper tile)
#pragma unroll
    for (int i = 0; i < 8; i++) {
        size_t row = (size_t)(m0 + ty * 8 + i) * NPTS + n0 + tx * 8;
        *(float4*)(C + row)     = make_float4(acc[i][0], acc[i][1], acc[i][2], acc[i][3]);
        *(float4*)(C + row + 4) = make_float4(acc[i][4], acc[i][5], acc[i][6], acc[i][7]);
    }
    // mirrored store (lower tile) — on diagonal tiles this duplicates equal values
#pragma unroll
    for (int j = 0; j < 8; j++) {
        size_t row = (size_t)(n0 + tx * 8 + j) * NPTS + m0 + ty * 8;
        *(float4*)(C + row)     = make_float4(acc[0][j], acc[1][j], acc[2][j], acc[3][j]);
        *(float4*)(C + row + 4) = make_float4(acc[4][j], acc[5][j], acc[6][j], acc[7][j]);
    }
}

// ---------------- squared norms ----------------
__global__ void sq_kernel(const float* __restrict__ X, int Kd) {
    int i = blockIdx.x * blockDim.x + threadIdx.x;
    if (i < BB * NPTS) {
        const float* p = X + (size_t)i * Kd;
        float s = 0.f;
        for (int f = 0; f < Kd; f++) s += p[f] * p[f];
        g_sq[i] = s;
    }
}

// ---------------- top-K smallest d2 per row, warp per row ----------------
__device__ __forceinline__ bool dless(float a, int ia, float bv, int ib) {
    return (a < bv) || (a == bv && ia < ib);
}

__global__ void topk_kernel(const float* __restrict__ dotm) {
    int gwarp = (blockIdx.x * blockDim.x + threadIdx.x) >> 5;
    int lane = threadIdx.x & 31;
    if (gwarp >= BB * NPTS) return;
    int b = gwarp / NPTS, i = gwarp % NPTS;
    const float* drow = dotm + ((size_t)b * NPTS + i) * NPTS;
    float sqi = g_sq[b * NPTS + i];

    float best[KNN];
    int bidx[KNN];
#pragma unroll
    for (int m = 0; m < KNN; m++) { best[m] = 3.0e38f; bidx[m] = 0x7fffffff; }

    for (int j = lane; j < NPTS; j += 32) {
        float d2 = sqi + g_sq[b * NPTS + j] - 2.0f * drow[j];
        if (dless(d2, j, best[KNN - 1], bidx[KNN - 1])) {
            int m = KNN - 1;
#pragma unroll
            for (int t = KNN - 1; t > 0; t--) {
                if (m == t && dless(d2, j, best[t - 1], bidx[t - 1])) {
                    best[t] = best[t - 1]; bidx[t] = bidx[t - 1]; m = t - 1;
                }
            }
            best[m] = d2; bidx[m] = j;
        }
    }

    int ptr = 0;
    for (int r = 0; r < KNN; r++) {
        float v = (ptr < KNN) ? best[ptr] : 3.0e38f;
        int jj = (ptr < KNN) ? bidx[ptr] : 0x7fffffff;
        float mv = v; int mj = jj;
#pragma unroll
        for (int off = 16; off > 0; off >>= 1) {
            float ov = __shfl_down_sync(0xffffffffu, mv, off);
            int oj = __shfl_down_sync(0xffffffffu, mj, off);
            if (dless(ov, oj, mv, mj)) { mv = ov; mj = oj; }
        }
        mv = __shfl_sync(0xffffffffu, mv, 0);
        mj = __shfl_sync(0xffffffffu, mj, 0);
        if (jj == mj && v == mv) ptr++;
        if (lane == 0) g_idx[((size_t)b * NPTS + i) * KNN + r] = mj;
    }
}

// ---------------- gather-max edge conv epilogue ----------------
// out[n,o] = leaky( Z[n,o] - Y[n,o] + max_{j in knn(n)} Y[j,o] )
__global__ __launch_bounds__(256) void gathermax_kernel(const float* __restrict__ Z,
                                                        const float* __restrict__ Y,
                                                        const int* __restrict__ idx,
                                                        float* __restrict__ Out,
                                                        int fout) {
    int bn = blockIdx.x;             // b*NPTS + n
    int b = bn >> 11;
    const int* ip = idx + (size_t)bn * KNN;
    __shared__ int nb[KNN];
    if (threadIdx.x < KNN) nb[threadIdx.x] = ip[threadIdx.x];
    __syncthreads();

    const float* Yb = Y + (size_t)b * NPTS * fout;
    size_t base = (size_t)bn * fout;

    for (int o = threadIdx.x * 4; o < fout; o += blockDim.x * 4) {
        float4 m = make_float4(-3.0e38f, -3.0e38f, -3.0e38f, -3.0e38f);
#pragma unroll
        for (int k = 0; k < KNN; k++) {
            float4 v = *(const float4*)(Yb + (size_t)nb[k] * fout + o);
            m.x = fmaxf(m.x, v.x);
            m.y = fmaxf(m.y, v.y);
            m.z = fmaxf(m.z, v.z);
            m.w = fmaxf(m.w, v.w);
        }
        float4 z = *(const float4*)(Z + base + o);
        float4 y = *(const float4*)(Y + base + o);
        float4 h;
        h.x = z.x - y.x + m.x;
        h.y = z.y - y.y + m.y;
        h.z = z.z - y.z + m.z;
        h.w = z.w - y.w + m.w;
        h.x = (h.x > 0.f) ? h.x : SLOPE * h.x;
        h.y = (h.y > 0.f) ? h.y : SLOPE * h.y;
        h.z = (h.z > 0.f) ? h.z : SLOPE * h.z;
        h.w = (h.w > 0.f) ? h.w : SLOPE * h.w;
        *(float4*)(Out + base + o) = h;
    }
}

// ---------------- global max pool over N ----------------
__global__ void pool_kernel(const float* __restrict__ H, int Fo) {
    int b = blockIdx.y;
    int o = blockIdx.x * blockDim.x + threadIdx.x;
    if (o < Fo) {
        float m = -3.0e38f;
        for (int n = 0; n < NPTS; n++)
            m = fmaxf(m, H[((size_t)b * NPTS + n) * Fo + o]);
        g_pool[b * Fo + o] = m;
    }
}

// ---------------- small MLP layer (no activation per reference) ----------------
__global__ void mlp_kernel(const float* __restrict__ A, const float* __restrict__ W,
                           const float* __restrict__ bias, float* __restrict__ C,
                           int M, int Kd, int Nn) {
    for (int i = threadIdx.x; i < M * Nn; i += blockDim.x) {
        int m = i / Nn, o = i % Nn;
        float s = bias[o];
        for (int f = 0; f < Kd; f++) s += A[(size_t)m * Kd + f] * W[(size_t)f * Nn + o];
        C[i] = s;
    }
}

// ---------------- launcher ----------------
extern "C" void kernel_launch(void* const* d_in, const int* in_sizes, int n_in,
                              void* d_out, int out_size) {
    const float* x = (const float*)d_in[0];
    const float* w[5];
    const float* bs[5];
    for (int l = 0; l < 5; l++) {
        w[l] = (const float*)d_in[1 + 2 * l];
        bs[l] = (const float*)d_in[2 + 2 * l];
    }
    const float* m0w = (const float*)d_in[11];
    const float* m0b = (const float*)d_in[12];
    const float* m1w = (const float*)d_in[13];
    const float* m1b = (const float*)d_in[14];
    const float* m2w = (const float*)d_in[15];
    const float* m2b = (const float*)d_in[16];
    float* out = (float*)d_out;

    float *feat_a, *feat_b, *centerp, *dotp, *poolp, *m1p, *m2p;
    cudaGetSymbolAddress((void**)&feat_a, g_feat_a);
    cudaGetSymbolAddress((void**)&feat_b, g_feat_b);
    cudaGetSymbolAddress((void**)&centerp, g_center);
    cudaGetSymbolAddress((void**)&dotp, g_dot);
    cudaGetSymbolAddress((void**)&poolp, g_pool);
    cudaGetSymbolAddress((void**)&m1p, g_m1);
    cudaGetSymbolAddress((void**)&m2p, g_m2);
    int* idxp;
    cudaGetSymbolAddress((void**)&idxp, g_idx);

    const int fins[5] = {3, 64, 128, 256, 512};
    const int fouts[5] = {64, 128, 256, 512, 1024};
    float* bufs[2] = {feat_a, feat_b};

    const float* cur = x;
    for (int l = 0; l < 5; l++) {
        int fin = fins[l], fout = fouts[l];
        float* yp = dotp;   // reuse dot scratch for Y after topk consumes it
        int gx = (fout + 127) / 128;

        sgemm_nt_sym<<<dim3(NPTS / 128, NPTS / 128, BB), 256>>>(cur, dotp, fin);
        sq_kernel<<<(BB * NPTS + 255) / 256, 256>>>(cur, fin);
        topk_kernel<<<(BB * NPTS) / 8, 256>>>(dotp);
        // Z = X*W1 + b
        sgemm_nn<<<dim3(gx, (BB * NPTS) / 128), 256>>>(cur, w[l], bs[l], centerp, fin, fout);
        // Y = X*W2 (overwrites dot scratch; topk already done in stream order)
        sgemm_nn<<<dim3(gx, (BB * NPTS) / 128), 256>>>(cur, w[l] + (size_t)fin * fout,
                                                       nullptr, yp, fin, fout);
        gathermax_kernel<<<BB * NPTS, 256>>>(centerp, yp, idxp, bufs[l & 1], fout);
        cur = bufs[l & 1];
    }

    pool_kernel<<<dim3(MAXF / 256, BB), 256>>>(cur, MAXF);
    mlp_kernel<<<1, 1024>>>(poolp, m0w, m0b, m1p, BB, 1024, 128);
    mlp_kernel<<<1, 512>>>(m1p, m1w, m1b, m2p, BB, 128, 64);
    mlp_kernel<<<1, 256>>>(m2p, m2w, m2b, out, BB, 64, 1);
}

// round 4
// speedup vs baseline: 2.7471x; 1.0459x over previous
#include <cuda_runtime.h>
#include <cstdint>

#define BB   8
#define NPTS 2048
#define KNN  10
#define MAXF 1024
#define SLOPE 0.2f
#define KT   16

// ---------------- static scratch (no allocations allowed) ----------------
__device__ float g_feat_a[BB * NPTS * MAXF];                 // 64 MB
__device__ float g_feat_b[BB * NPTS * MAXF];                 // 64 MB
__device__ float g_center[BB * NPTS * MAXF];                 // 64 MB
__device__ float g_dot[(size_t)BB * NPTS * NPTS];            // 128 MB (reused as Y after topk)
__device__ float g_sq[BB * NPTS];
__device__ int   g_idx[BB * NPTS * KNN];
__device__ float g_pool[BB * MAXF];
__device__ float g_m1[BB * 128];
__device__ float g_m2[BB * 64];

// ---------------- packed f32x2 helpers (Blackwell FFMA2) ----------------
__device__ __forceinline__ unsigned long long f32x2_dup(float x) {
    unsigned long long r;
    asm("mov.b64 %0, {%1, %2};" : "=l"(r) : "f"(x), "f"(x));
    return r;
}
__device__ __forceinline__ void f32x2_fma(unsigned long long& d, unsigned long long a,
                                          unsigned long long b) {
    asm("fma.rn.f32x2 %0, %1, %2, %0;" : "+l"(d) : "l"(a), "l"(b));
}
__device__ __forceinline__ float2 f32x2_unpack(unsigned long long v) {
    float2 r;
    asm("mov.b64 {%0, %1}, %2;" : "=f"(r.x), "=f"(r.y) : "l"(v));
    return r;
}

// =====================================================================
// 128x128 register-blocked SGEMM (FFMA2), NN: C = A @ W (+bias)
// 256 threads, 8x(4 x f32x2) acc per thread, KT=16.
// =====================================================================
__global__ __launch_bounds__(256) void sgemm_nn(const float* __restrict__ A,
                                                const float* __restrict__ W,
                                                const float* __restrict__ bias,
                                                float* __restrict__ C,
                                                int Kd, int Nn) {
    __shared__ float As[KT][128];
    __shared__ float Bs[KT][128];
    int tid = threadIdx.x;
    int tx = tid & 15, ty = tid >> 4;
    int m0 = blockIdx.y * 128, o0 = blockIdx.x * 128;
    const bool kfast = (Kd % KT) == 0;

    unsigned long long acc2[8][4];
#pragma unroll
    for (int i = 0; i < 8; i++)
#pragma unroll
        for (int p = 0; p < 4; p++) acc2[i][p] = 0ull;   // (0.f,0.f)

    for (int f0 = 0; f0 < Kd; f0 += KT) {
#pragma unroll
        for (int it = 0; it < 2; it++) {
            int e = tid + it * 256;
            int r = e >> 2;
            int kb = (e & 3) * 4;
            if (kfast) {
                float4 v = *(const float4*)(A + (size_t)(m0 + r) * Kd + f0 + kb);
                As[kb + 0][r] = v.x; As[kb + 1][r] = v.y;
                As[kb + 2][r] = v.z; As[kb + 3][r] = v.w;
            } else {
#pragma unroll
                for (int j = 0; j < 4; j++) {
                    int f = f0 + kb + j;
                    As[kb + j][r] = (f < Kd) ? A[(size_t)(m0 + r) * Kd + f] : 0.f;
                }
            }
        }
#pragma unroll
        for (int it = 0; it < 2; it++) {
            int e = tid + it * 256;
            int k = e >> 5;
            int ob = (e & 31) * 4;
            float4 v = make_float4(0.f, 0.f, 0.f, 0.f);
            if ((f0 + k) < Kd && (o0 + ob) < Nn)
                v = *(const float4*)(W + (size_t)(f0 + k) * Nn + o0 + ob);
            *(float4*)&Bs[k][ob] = v;
        }
        __syncthreads();
#pragma unroll
        for (int k = 0; k < KT; k++) {
            float a[8];
            *(float4*)&a[0] = *(const float4*)&As[k][ty * 8];
            *(float4*)&a[4] = *(const float4*)&As[k][ty * 8 + 4];
            unsigned long long b2[4];
            const unsigned long long* bp = (const unsigned long long*)&Bs[k][tx * 8];
#pragma unroll
            for (int p = 0; p < 4; p++) b2[p] = bp[p];
            unsigned long long ad[8];
#pragma unroll
            for (int i = 0; i < 8; i++) ad[i] = f32x2_dup(a[i]);
#pragma unroll
            for (int i = 0; i < 8; i++)
#pragma unroll
                for (int p = 0; p < 4; p++) f32x2_fma(acc2[i][p], ad[i], b2[p]);
        }
        __syncthreads();
    }

    int oc = o0 + tx * 8;
    if (oc < Nn) {
#pragma unroll
        for (int i = 0; i < 8; i++) {
            size_t row = (size_t)(m0 + ty * 8 + i) * Nn;
            float c[8];
#pragma unroll
            for (int p = 0; p < 4; p++) {
                float2 u = f32x2_unpack(acc2[i][p]);
                c[2 * p] = u.x; c[2 * p + 1] = u.y;
            }
            if (bias) {
#pragma unroll
                for (int j = 0; j < 8; j++) c[j] += bias[oc + j];
            }
            *(float4*)(C + row + oc)     = make_float4(c[0], c[1], c[2], c[3]);
            *(float4*)(C + row + oc + 4) = make_float4(c[4], c[5], c[6], c[7]);
        }
    }
}

// =====================================================================
// Symmetric NT SGEMM (FFMA2) per batch: C = X @ X^T, upper tiles only,
// mirrored into lower half.
// =====================================================================
__global__ __launch_bounds__(256) void sgemm_nt_sym(const float* __restrict__ Xall,
                                                    float* __restrict__ Call, int Kd) {
    int m0 = blockIdx.y * 128, n0 = blockIdx.x * 128;
    if (n0 < m0) return;
    int b = blockIdx.z;
    const float* X = Xall + (size_t)b * NPTS * Kd;
    float* C = Call + (size_t)b * NPTS * NPTS;

    __shared__ float As[KT][128];
    __shared__ float Bs[KT][128];
    int tid = threadIdx.x;
    int tx = tid & 15, ty = tid >> 4;
    const bool kfast = (Kd % KT) == 0;

    unsigned long long acc2[8][4];
#pragma unroll
    for (int i = 0; i < 8; i++)
#pragma unroll
        for (int p = 0; p < 4; p++) acc2[i][p] = 0ull;

    for (int f0 = 0; f0 < Kd; f0 += KT) {
#pragma unroll
        for (int it = 0; it < 2; it++) {
            int e = tid + it * 256;
            int r = e >> 2;
            int kb = (e & 3) * 4;
            if (kfast) {
                float4 va = *(const float4*)(X + (size_t)(m0 + r) * Kd + f0 + kb);
                As[kb + 0][r] = va.x; As[kb + 1][r] = va.y;
                As[kb + 2][r] = va.z; As[kb + 3][r] = va.w;
                float4 vb = *(const float4*)(X + (size_t)(n0 + r) * Kd + f0 + kb);
                Bs[kb + 0][r] = vb.x; Bs[kb + 1][r] = vb.y;
                Bs[kb + 2][r] = vb.z; Bs[kb + 3][r] = vb.w;
            } else {
#pragma unroll
                for (int j = 0; j < 4; j++) {
                    int f = f0 + kb + j;
                    As[kb + j][r] = (f < Kd) ? X[(size_t)(m0 + r) * Kd + f] : 0.f;
                    Bs[kb + j][r] = (f < Kd) ? X[(size_t)(n0 + r) * Kd + f] : 0.f;
                }
            }
        }
        __syncthreads();
#pragma unroll
        for (int k = 0; k < KT; k++) {
            float a[8];
            *(float4*)&a[0] = *(const float4*)&As[k][ty * 8];
            *(float4*)&a[4] = *(const float4*)&As[k][ty * 8 + 4];
            unsigned long long b2[4];
            const unsigned long long* bp = (const unsigned long long*)&Bs[k][tx * 8];
#pragma unroll
            for (int p = 0; p < 4; p++) b2[p] = bp[p];
            unsigned long long ad[8];
#pragma unroll
            for (int i = 0; i < 8; i++) ad[i] = f32x2_dup(a[i]);
#pragma unroll
            for (int i = 0; i < 8; i++)
#pragma unroll
                for (int p = 0; p < 4; p++) f32x2_fma(acc2[i][p], ad[i], b2[p]);
        }
        __syncthreads();
    }

    float c[8][8];
#pragma unroll
    for (int i = 0; i < 8; i++)
#pragma unroll
        for (int p = 0; p < 4; p++) {
            float2 u = f32x2_unpack(acc2[i][p]);
            c[i][2 * p] = u.x; c[i][2 * p + 1] = u.y;
        }

    // upper tile store
#pragma unroll
    for (int i = 0; i < 8; i++) {
        size_t row = (size_t)(m0 + ty * 8 + i) * NPTS + n0 + tx * 8;
        *(float4*)(C + row)     = make_float4(c[i][0], c[i][1], c[i][2], c[i][3]);
        *(float4*)(C + row + 4) = make_float4(c[i][4], c[i][5], c[i][6], c[i][7]);
    }
    // mirrored lower tile store (diagonal tiles: duplicate equal values)
#pragma unroll
    for (int j = 0; j < 8; j++) {
        size_t row = (size_t)(n0 + tx * 8 + j) * NPTS + m0 + ty * 8;
        *(float4*)(C + row)     = make_float4(c[0][j], c[1][j], c[2][j], c[3][j]);
        *(float4*)(C + row + 4) = make_float4(c[4][j], c[5][j], c[6][j], c[7][j]);
    }
}

// ---------------- squared norms ----------------
__global__ void sq_kernel(const float* __restrict__ X, int Kd) {
    int i = blockIdx.x * blockDim.x + threadIdx.x;
    if (i < BB * NPTS) {
        const float* p = X + (size_t)i * Kd;
        float s = 0.f;
        for (int f = 0; f < Kd; f++) s += p[f] * p[f];
        g_sq[i] = s;
    }
}

// ---------------- top-K smallest d2 per row, warp per row ----------------
__device__ __forceinline__ bool dless(float a, int ia, float bv, int ib) {
    return (a < bv) || (a == bv && ia < ib);
}

__global__ void topk_kernel(const float* __restrict__ dotm) {
    int gwarp = (blockIdx.x * blockDim.x + threadIdx.x) >> 5;
    int lane = threadIdx.x & 31;
    if (gwarp >= BB * NPTS) return;
    int b = gwarp / NPTS, i = gwarp % NPTS;
    const float* drow = dotm + ((size_t)b * NPTS + i) * NPTS;
    float sqi = g_sq[b * NPTS + i];

    float best[KNN];
    int bidx[KNN];
#pragma unroll
    for (int m = 0; m < KNN; m++) { best[m] = 3.0e38f; bidx[m] = 0x7fffffff; }

    for (int j = lane; j < NPTS; j += 32) {
        float d2 = sqi + g_sq[b * NPTS + j] - 2.0f * drow[j];
        if (dless(d2, j, best[KNN - 1], bidx[KNN - 1])) {
            int m = KNN - 1;
#pragma unroll
            for (int t = KNN - 1; t > 0; t--) {
                if (m == t && dless(d2, j, best[t - 1], bidx[t - 1])) {
                    best[t] = best[t - 1]; bidx[t] = bidx[t - 1]; m = t - 1;
                }
            }
            best[m] = d2; bidx[m] = j;
        }
    }

    int ptr = 0;
    for (int r = 0; r < KNN; r++) {
        float v = (ptr < KNN) ? best[ptr] : 3.0e38f;
        int jj = (ptr < KNN) ? bidx[ptr] : 0x7fffffff;
        float mv = v; int mj = jj;
#pragma unroll
        for (int off = 16; off > 0; off >>= 1) {
            float ov = __shfl_down_sync(0xffffffffu, mv, off);
            int oj = __shfl_down_sync(0xffffffffu, mj, off);
            if (dless(ov, oj, mv, mj)) { mv = ov; mj = oj; }
        }
        mv = __shfl_sync(0xffffffffu, mv, 0);
        mj = __shfl_sync(0xffffffffu, mj, 0);
        if (jj == mj && v == mv) ptr++;
        if (lane == 0) g_idx[((size_t)b * NPTS + i) * KNN + r] = mj;
    }
}

// ---------------- gather-max edge conv epilogue ----------------
// out[n,o] = leaky( Z[n,o] - Y[n,o] + max_{j in knn(n)} Y[j,o] )
__global__ __launch_bounds__(256) void gathermax_kernel(const float* __restrict__ Z,
                                                        const float* __restrict__ Y,
                                                        const int* __restrict__ idx,
                                                        float* __restrict__ Out,
                                                        int fout) {
    int bn = blockIdx.x;
    int b = bn >> 11;
    const int* ip = idx + (size_t)bn * KNN;
    __shared__ int nb[KNN];
    if (threadIdx.x < KNN) nb[threadIdx.x] = ip[threadIdx.x];
    __syncthreads();

    const float* Yb = Y + (size_t)b * NPTS * fout;
    size_t base = (size_t)bn * fout;

    for (int o = threadIdx.x * 4; o < fout; o += blockDim.x * 4) {
        float4 m = make_float4(-3.0e38f, -3.0e38f, -3.0e38f, -3.0e38f);
#pragma unroll
        for (int k = 0; k < KNN; k++) {
            float4 v = *(const float4*)(Yb + (size_t)nb[k] * fout + o);
            m.x = fmaxf(m.x, v.x);
            m.y = fmaxf(m.y, v.y);
            m.z = fmaxf(m.z, v.z);
            m.w = fmaxf(m.w, v.w);
        }
        float4 z = *(const float4*)(Z + base + o);
        float4 y = *(const float4*)(Y + base + o);
        float4 h;
        h.x = z.x - y.x + m.x;
        h.y = z.y - y.y + m.y;
        h.z = z.z - y.z + m.z;
        h.w = z.w - y.w + m.w;
        h.x = (h.x > 0.f) ? h.x : SLOPE * h.x;
        h.y = (h.y > 0.f) ? h.y : SLOPE * h.y;
        h.z = (h.z > 0.f) ? h.z : SLOPE * h.z;
        h.w = (h.w > 0.f) ? h.w : SLOPE * h.w;
        *(float4*)(Out + base + o) = h;
    }
}

// ---------------- global max pool over N ----------------
__global__ void pool_kernel(const float* __restrict__ H, int Fo) {
    int b = blockIdx.y;
    int o = blockIdx.x * blockDim.x + threadIdx.x;
    if (o < Fo) {
        float m = -3.0e38f;
        for (int n = 0; n < NPTS; n++)
            m = fmaxf(m, H[((size_t)b * NPTS + n) * Fo + o]);
        g_pool[b * Fo + o] = m;
    }
}

// ---------------- small MLP layer ----------------
__global__ void mlp_kernel(const float* __restrict__ A, const float* __restrict__ W,
                           const float* __restrict__ bias, float* __restrict__ C,
                           int M, int Kd, int Nn) {
    for (int i = threadIdx.x; i < M * Nn; i += blockDim.x) {
        int m = i / Nn, o = i % Nn;
        float s = bias[o];
        for (int f = 0; f < Kd; f++) s += A[(size_t)m * Kd + f] * W[(size_t)f * Nn + o];
        C[i] = s;
    }
}

// ---------------- launcher ----------------
extern "C" void kernel_launch(void* const* d_in, const int* in_sizes, int n_in,
                              void* d_out, int out_size) {
    const float* x = (const float*)d_in[0];
    const float* w[5];
    const float* bs[5];
    for (int l = 0; l < 5; l++) {
        w[l] = (const float*)d_in[1 + 2 * l];
        bs[l] = (const float*)d_in[2 + 2 * l];
    }
    const float* m0w = (const float*)d_in[11];
    const float* m0b = (const float*)d_in[12];
    const float* m1w = (const float*)d_in[13];
    const float* m1b = (const float*)d_in[14];
    const float* m2w = (const float*)d_in[15];
    const float* m2b = (const float*)d_in[16];
    float* out = (float*)d_out;

    float *feat_a, *feat_b, *centerp, *dotp, *poolp, *m1p, *m2p;
    cudaGetSymbolAddress((void**)&feat_a, g_feat_a);
    cudaGetSymbolAddress((void**)&feat_b, g_feat_b);
    cudaGetSymbolAddress((void**)&centerp, g_center);
    cudaGetSymbolAddress((void**)&dotp, g_dot);
    cudaGetSymbolAddress((void**)&poolp, g_pool);
    cudaGetSymbolAddress((void**)&m1p, g_m1);
    cudaGetSymbolAddress((void**)&m2p, g_m2);
    int* idxp;
    cudaGetSymbolAddress((void**)&idxp, g_idx);

    const int fins[5] = {3, 64, 128, 256, 512};
    const int fouts[5] = {64, 128, 256, 512, 1024};
    float* bufs[2] = {feat_a, feat_b};

    const float* cur = x;
    for (int l = 0; l < 5; l++) {
        int fin = fins[l], fout = fouts[l];
        float* yp = dotp;   // reuse dot scratch for Y after topk consumes it
        int gx = (fout + 127) / 128;

        sgemm_nt_sym<<<dim3(NPTS / 128, NPTS / 128, BB), 256>>>(cur, dotp, fin);
        sq_kernel<<<(BB * NPTS + 255) / 256, 256>>>(cur, fin);
        topk_kernel<<<(BB * NPTS) / 8, 256>>>(dotp);
        sgemm_nn<<<dim3(gx, (BB * NPTS) / 128), 256>>>(cur, w[l], bs[l], centerp, fin, fout);
        sgemm_nn<<<dim3(gx, (BB * NPTS) / 128), 256>>>(cur, w[l] + (size_t)fin * fout,
                                                       nullptr, yp, fin, fout);
        gathermax_kernel<<<BB * NPTS, 256>>>(centerp, yp, idxp, bufs[l & 1], fout);
        cur = bufs[l & 1];
    }

    pool_kernel<<<dim3(MAXF / 256, BB), 256>>>(cur, MAXF);
    mlp_kernel<<<1, 1024>>>(poolp, m0w, m0b, m1p, BB, 1024, 128);
    mlp_kernel<<<1, 512>>>(m1p, m1w, m1b, m2p, BB, 128, 64);
    mlp_kernel<<<1, 256>>>(m2p, m2w, m2b, out, BB, 64, 1);
}